// round 7
// baseline (speedup 1.0000x reference)
#include <cuda_runtime.h>

#define BB 512
#define TT 512
#define DD 128
#define LL 256
#define G4 1024
#define NCTA 128
#define NTHR 512
#define NRB 4            // row blocks
#define RBCTA 32         // CTAs per row-block barrier group
#define ZST 34           // zsm row stride (even: float2-aligned, <=4-way conflicts)

typedef unsigned long long ull;

// Persistent state (static __device__ globals — no allocation)
__device__ float g_H[2][LL][BB];          // hidden state [feature][batch]
__device__ float g_encT[TT][DD][BB];      // encoder inputs transposed
__device__ float g_xdT[2][DD][BB];        // decoder input ping-pong, transposed
__device__ unsigned int g_count[NRB * 32];  // one counter per 128B
__device__ unsigned int g_gen[NRB * 32];    // monotonic generation

// Split barrier over the 32 CTAs of one row block. Snapshot-based wait:
// robust across graph replays (no global reset needed).
__device__ __forceinline__ void rb_arrive(int rb, unsigned int* snap) {
    __syncthreads();                     // all CTA work done before arriving
    if (threadIdx.x == 0) {
        volatile unsigned int* gp = &g_gen[rb * 32];
        *snap = *gp;                     // snapshot BEFORE own arrive
        __threadfence();
        if (atomicAdd(&g_count[rb * 32], 1u) == RBCTA - 1u) {
            g_count[rb * 32] = 0u;
            __threadfence();
            atomicAdd(&g_gen[rb * 32], 1u);   // release
        }
    }
}
__device__ __forceinline__ void rb_wait(int rb, unsigned int snap) {
    if (threadIdx.x == 0) {
        volatile unsigned int* gp = &g_gen[rb * 32];
        while (*gp == snap) { }
        __threadfence();
    }
    __syncthreads();
}

__device__ __forceinline__ float sigm(float x) { return 1.0f / (1.0f + __expf(-x)); }

__device__ __forceinline__ ull pack2(float lo, float hi) {
    ull r; asm("mov.b64 %0, {%1, %2};" : "=l"(r) : "f"(lo), "f"(hi)); return r;
}
__device__ __forceinline__ void ffma2(ull& d, ull a, ull b) {
    asm("fma.rn.f32x2 %0, %1, %2, %0;" : "+l"(d) : "l"(a), "l"(b));
}

// acc[i][jp] (+)= A[k][row i] * W[k][colpair jp]; 16 FFMA2 per k.
// Column-pair packing: W pairs load directly as ulonglong2 from smem (no movs);
// A rows duplicated with 4 pack2 per k.
// A: [K][BB] batch-contiguous; w: [K][32], thread uses 8 cols at 16B-aligned offset.
__device__ __forceinline__ void gemm48(
    const float* __restrict__ A,
    const float* __restrict__ w,      // pre-offset to this thread's 8 cols
    int kcnt, ull acc[4][4])
{
    #pragma unroll 4
    for (int k = 0; k < kcnt; k++) {
        float4 av = *reinterpret_cast<const float4*>(A + (size_t)k * BB);
        ulonglong2 wlo = *reinterpret_cast<const ulonglong2*>(w + k * 32);
        ulonglong2 whi = *reinterpret_cast<const ulonglong2*>(w + k * 32 + 4);
        ull a0 = pack2(av.x, av.x);
        ull a1 = pack2(av.y, av.y);
        ull a2 = pack2(av.z, av.z);
        ull a3 = pack2(av.w, av.w);
        ffma2(acc[0][0], a0, wlo.x);
        ffma2(acc[0][1], a0, wlo.y);
        ffma2(acc[0][2], a0, whi.x);
        ffma2(acc[0][3], a0, whi.y);
        ffma2(acc[1][0], a1, wlo.x);
        ffma2(acc[1][1], a1, wlo.y);
        ffma2(acc[1][2], a1, whi.x);
        ffma2(acc[1][3], a1, whi.y);
        ffma2(acc[2][0], a2, wlo.x);
        ffma2(acc[2][1], a2, wlo.y);
        ffma2(acc[2][2], a2, whi.x);
        ffma2(acc[2][3], a2, whi.y);
        ffma2(acc[3][0], a3, wlo.x);
        ffma2(acc[3][1], a3, wlo.y);
        ffma2(acc[3][2], a3, whi.x);
        ffma2(acc[3][3], a3, whi.y);
    }
}

// Store/load a thread's 16 col-pair accumulators to/from its zsm quarter.
// acc[i][jp] = cols (2jp,2jp+1) of row tx*4+i -> 8B-aligned u64 (ZST even).
__device__ __forceinline__ void z_store(float* zs, int tx, int ty, const ull acc[4][4]) {
    #pragma unroll
    for (int i = 0; i < 4; i++)
        #pragma unroll
        for (int jp = 0; jp < 4; jp++)
            *reinterpret_cast<ull*>(&zs[(tx * 4 + i) * ZST + ty * 8 + jp * 2]) = acc[i][jp];
}
__device__ __forceinline__ void z_load(const float* zs, int tx, int ty, ull acc[4][4]) {
    #pragma unroll
    for (int i = 0; i < 4; i++)
        #pragma unroll
        for (int jp = 0; jp < 4; jp++)
            acc[i][jp] = *reinterpret_cast<const ull*>(&zs[(tx * 4 + i) * ZST + ty * 8 + jp * 2]);
}

// Activation + h write. Thread -> (2 rows, 1 unit); FIXED mapping (c lives here).
// Caller must have stored all 4 z-partials and done __syncthreads().
__device__ __forceinline__ void activation(
    const float* __restrict__ zsm, const float* __restrict__ bsm,
    float c2[2], float* __restrict__ hOutT, int b0, int nb, int tid)
{
    int u  = tid >> 6;              // 0..7
    int r0 = (tid & 63) * 2;
    float hv[2];
    #pragma unroll
    for (int i = 0; i < 2; i++) {
        int r = r0 + i;
        float zi = bsm[u],      zf = bsm[8 + u];
        float zg = bsm[16 + u], zo = bsm[24 + u];
        #pragma unroll
        for (int p = 0; p < 4; p++) {
            const float* zp = zsm + p * (128 * ZST) + r * ZST;
            zi += zp[u];
            zf += zp[8 + u];
            zg += zp[16 + u];
            zo += zp[24 + u];
        }
        float ig = sigm(zi);
        float fg = sigm(zf);
        float gg = fmaxf(zg, 0.0f);
        float og = sigm(zo);
        float cn = fg * c2[i] + ig * gg;
        c2[i] = cn;
        hv[i] = og * fmaxf(cn, 0.0f);
    }
    *reinterpret_cast<float2*>(&hOutT[(nb * 8 + u) * BB + b0 + r0]) =
        make_float2(hv[0], hv[1]);
}

// Tiled transpose: encIn[b][t][k] -> g_encT[t][k][b]
extern "C" __global__ void __launch_bounds__(256)
transpose_enc_kernel(const float* __restrict__ in)
{
    __shared__ float tile[32][33];
    int t  = blockIdx.z;
    int k0 = blockIdx.y * 32;
    int b0 = blockIdx.x * 32;
    int tx = threadIdx.x, ty = threadIdx.y;  // 32 x 8
    #pragma unroll
    for (int i = 0; i < 32; i += 8)
        tile[ty + i][tx] = in[(size_t)(b0 + ty + i) * (TT * DD) + t * DD + k0 + tx];
    __syncthreads();
    #pragma unroll
    for (int i = 0; i < 32; i += 8)
        g_encT[t][k0 + ty + i][b0 + tx] = tile[tx][ty + i];
}

extern "C" __global__ void __launch_bounds__(NTHR, 1)
lstm_ae_kernel(const float* __restrict__ decIn,
               const float* __restrict__ W0, const float* __restrict__ U0, const float* __restrict__ b0g,
               const float* __restrict__ W1, const float* __restrict__ U1, const float* __restrict__ b1g,
               const float* __restrict__ Wd, const float* __restrict__ Ud, const float* __restrict__ bdg,
               const float* __restrict__ Wo, const float* __restrict__ bog,
               float* __restrict__ outp)
{
    extern __shared__ float smem[];
    float* w0sm = smem;                 // [384][32]
    float* w1sm = w0sm + 384 * 32;      // [256][32]  (W1+U1 fused: x == h for layer 1)
    float* wdsm = w1sm + 256 * 32;      // [384][32]
    float* wosm = wdsm + 384 * 32;      // [256][4]
    float* b0sm = wosm + 256 * 4;       // 32
    float* b1sm = b0sm + 32;            // 32
    float* bdsm = b1sm + 32;            // 32
    float* bosm = bdsm + 32;            // 4 (+12 pad)
    float* zsm  = bosm + 16;            // [4][128][ZST]  (16B-aligned: offset 34928 floats)

    int tid = threadIdx.x;
    int nb = blockIdx.x & 31;           // hidden-unit block (8 units)
    int rb = blockIdx.x >> 5;           // row block (128 batch rows)
    int b0 = rb * 128;

    int q    = tid >> 7;                // K quarter
    int qtid = tid & 127;
    int tx   = qtid & 31;               // rows tx*4 .. +3
    int ty   = qtid >> 5;               // colpairs at ty*8 (warp-uniform)
    int colBase = b0 + tx * 4;
    float* zq = zsm + q * (128 * ZST);
    const float* w0ty = w0sm + ty * 8;
    const float* w1ty = w1sm + ty * 8;
    const float* wdty = wdsm + ty * 8;

    // ---- one-time weight preload, layout [k][32 local cols] ----
    for (int idx = tid; idx < 384 * 32; idx += NTHR) {
        int k = idx >> 5, lc = idx & 31;
        int gcol = (lc >> 3) * LL + nb * 8 + (lc & 7);
        w0sm[idx] = (k < DD) ? W0[k * G4 + gcol] : U0[(k - DD) * G4 + gcol];
        wdsm[idx] = (k < DD) ? Wd[k * G4 + gcol] : Ud[(k - DD) * G4 + gcol];
    }
    for (int idx = tid; idx < 256 * 32; idx += NTHR) {
        int k = idx >> 5, lc = idx & 31;
        int gcol = (lc >> 3) * LL + nb * 8 + (lc & 7);
        w1sm[idx] = W1[k * G4 + gcol] + U1[k * G4 + gcol];
    }
    for (int idx = tid; idx < 256 * 4; idx += NTHR) {
        int k = idx >> 2, j = idx & 3;
        wosm[idx] = Wo[k * DD + nb * 4 + j];
    }
    if (tid < 32) {
        int gcol = (tid >> 3) * LL + nb * 8 + (tid & 7);
        b0sm[tid] = b0g[gcol];
        b1sm[tid] = b1g[gcol];
        bdsm[tid] = bdg[gcol];
    }
    if (tid < 4) bosm[tid] = bog[nb * 4 + tid];

    // init: each CTA owns its (feature-slice x batch-slice) of g_H / g_xdT.
    for (int idx = tid; idx < 2 * 8 * 128; idx += NTHR) {
        int buf = idx >> 10, f = (idx >> 7) & 7, b = idx & 127;
        g_H[buf][nb * 8 + f][b0 + b] = 0.0f;
    }
    for (int idx = tid; idx < 4 * 128; idx += NTHR) {
        int f = idx >> 7, b = idx & 127;
        g_xdT[0][nb * 4 + f][b0 + b] = decIn[(size_t)(b0 + b) * (TT * DD) + nb * 4 + f];
    }
    __syncthreads();   // weights visible before prologue x-gemm

    // prologue: precompute x-part of encoder step 0 into zsm (CTA-local)
    {
        ull accx[4][4];
        #pragma unroll
        for (int i = 0; i < 4; i++)
            #pragma unroll
            for (int jp = 0; jp < 4; jp++) accx[i][jp] = 0ull;
        gemm48(&g_encT[0][q * 32][colBase], w0ty + (q * 32) * 32, 32, accx);
        z_store(zq, tx, ty, accx);
    }

    float c2[2] = {0.0f, 0.0f};
    unsigned int snap;
    rb_arrive(rb, &snap);   // init barrier (H, xdT visible)

    int cur = 0;
    // ---------------- encoder ----------------
    for (int t = 0; t < TT; t++) {
        // ===== layer 0: z = x_t @ W0 + h @ U0 =====
        rb_wait(rb, snap);                         // h_L1(t-1) visible
        {
            ull acc[4][4];
            z_load(zq, tx, ty, acc);               // own precomputed x-partials
            gemm48(&g_H[cur][q * 64][colBase], w0ty + (DD + q * 64) * 32, 64, acc);
            z_store(zq, tx, ty, acc);              // same thread, same cells
            __syncthreads();
            activation(zsm, b0sm, c2, &g_H[cur ^ 1][0][0], b0, nb, tid);
        }
        rb_arrive(rb, &snap);                      // h_L0(t) posted
        cur ^= 1;

        // ===== layer 1: z = h' @ (W1+U1) =====
        rb_wait(rb, snap);                         // h_L0(t) all visible
        {
            ull acc[4][4];
            #pragma unroll
            for (int i = 0; i < 4; i++)
                #pragma unroll
                for (int jp = 0; jp < 4; jp++) acc[i][jp] = 0ull;
            gemm48(&g_H[cur][q * 64][colBase], w1ty + (q * 64) * 32, 64, acc);
            z_store(zq, tx, ty, acc);
            __syncthreads();
            activation(zsm, b1sm, c2, &g_H[cur ^ 1][0][0], b0, nb, tid);
        }
        rb_arrive(rb, &snap);                      // h_L1(t) posted
        cur ^= 1;

        // ===== overlap zone: next step's x-partials while barrier settles =====
        if (t + 1 < TT) {
            ull accx[4][4];
            #pragma unroll
            for (int i = 0; i < 4; i++)
                #pragma unroll
                for (int jp = 0; jp < 4; jp++) accx[i][jp] = 0ull;
            gemm48(&g_encT[t + 1][q * 32][colBase], w0ty + (q * 32) * 32, 32, accx);
            z_store(zq, tx, ty, accx);             // safe: arrive's syncthreads passed
        }
    }
    // ---------------- decoder ----------------
    for (int t = 0; t < TT; t++) {
        rb_wait(rb, snap);                         // h(t-1) + xdT(t) visible
        {
            ull acc[4][4];
            #pragma unroll
            for (int i = 0; i < 4; i++)
                #pragma unroll
                for (int jp = 0; jp < 4; jp++) acc[i][jp] = 0ull;
            gemm48(&g_xdT[t & 1][q * 32][colBase], wdty + (q * 32) * 32, 32, acc);
            gemm48(&g_H[cur][q * 64][colBase], wdty + (DD + q * 64) * 32, 64, acc);
            z_store(zq, tx, ty, acc);
            __syncthreads();
            activation(zsm, bdsm, c2, &g_H[cur ^ 1][0][0], b0, nb, tid);
        }
        rb_arrive(rb, &snap);                      // h_dec(t) posted
        cur ^= 1;
        rb_wait(rb, snap);                         // all h_dec(t) visible

        // out = h @ out_W + out_b : 4 out-cols x 128 rows, K split in 4 chunks
        {
            int b  = tid & 127;
            int qq = tid >> 7;                     // 0..3 -> K chunk of 64
            const float* hP = &g_H[cur][qq * 64][b0 + b];
            const float* wP = wosm + qq * 64 * 4;
            float s0 = 0.f, s1 = 0.f, s2 = 0.f, s3 = 0.f;
            #pragma unroll 8
            for (int kk = 0; kk < 64; kk++) {
                float h = hP[(size_t)kk * BB];
                float4 w4 = *reinterpret_cast<const float4*>(wP + kk * 4);
                s0 = fmaf(h, w4.x, s0);
                s1 = fmaf(h, w4.y, s1);
                s2 = fmaf(h, w4.z, s2);
                s3 = fmaf(h, w4.w, s3);
            }
            if (qq) {
                float* zp = zsm + ((qq - 1) * 128 + b) * 4;
                zp[0] = s0; zp[1] = s1; zp[2] = s2; zp[3] = s3;
            }
            __syncthreads();
            if (qq == 0) {
                #pragma unroll
                for (int p = 0; p < 3; p++) {
                    const float* zp = zsm + (p * 128 + b) * 4;
                    s0 += zp[0]; s1 += zp[1]; s2 += zp[2]; s3 += zp[3];
                }
                s0 += bosm[0]; s1 += bosm[1]; s2 += bosm[2]; s3 += bosm[3];
                *reinterpret_cast<float4*>(
                    outp + (size_t)(b0 + b) * (TT * DD) + t * DD + nb * 4) =
                    make_float4(s0, s1, s2, s3);
                int nxt = (t + 1) & 1;
                g_xdT[nxt][nb * 4 + 0][b0 + b] = s0;
                g_xdT[nxt][nb * 4 + 1][b0 + b] = s1;
                g_xdT[nxt][nb * 4 + 2][b0 + b] = s2;
                g_xdT[nxt][nb * 4 + 3][b0 + b] = s3;
            }
        }
        rb_arrive(rb, &snap);                      // out(t)/xdT(t+1) posted
    }
}

extern "C" void kernel_launch(void* const* d_in, const int* in_sizes, int n_in,
                              void* d_out, int out_size)
{
    const float* encIn = (const float*)d_in[0];
    const float* decIn = (const float*)d_in[1];
    const float* W0    = (const float*)d_in[2];
    const float* U0    = (const float*)d_in[3];
    const float* b0    = (const float*)d_in[4];
    const float* W1    = (const float*)d_in[5];
    const float* U1    = (const float*)d_in[6];
    const float* b1    = (const float*)d_in[7];
    const float* Wd    = (const float*)d_in[8];
    const float* Ud    = (const float*)d_in[9];
    const float* bd    = (const float*)d_in[10];
    const float* Wo    = (const float*)d_in[11];
    const float* bo    = (const float*)d_in[12];
    float* outp = (float*)d_out;

    // 1) transpose encoder inputs
    {
        dim3 grid(BB / 32, DD / 32, TT);
        dim3 block(32, 8);
        transpose_enc_kernel<<<grid, block>>>(encIn);
    }

    // 2) persistent LSTM kernel
    // smem floats: 12288+8192+12288+1024+112 + 4*128*34 = 51312 (205.2KB)
    size_t smem_bytes = 51312 * sizeof(float);
    cudaFuncSetAttribute((const void*)lstm_ae_kernel,
                         cudaFuncAttributeMaxDynamicSharedMemorySize, (int)smem_bytes);
    lstm_ae_kernel<<<NCTA, NTHR, smem_bytes>>>(
        decIn, W0, U0, b0, W1, U1, b1, Wd, Ud, bd, Wo, bo, outp);
}

// round 8
// speedup vs baseline: 1.0638x; 1.0638x over previous
#include <cuda_runtime.h>

#define BB 512
#define TT 512
#define DD 128
#define LL 256
#define G4 1024
#define NCTA 128
#define NTHR 512
#define NRG 8            // row groups (64 rows each)
#define RGCTA 32         // CTAs per row-group barrier
#define ZST 33           // zsm row stride (bank-conflict pad)
#define ZHALF (4 * 64 * ZST)

typedef unsigned long long ull;

// Persistent state (static __device__ globals — no allocation)
__device__ float g_H[2][LL][BB];          // hidden state [feature][batch]
__device__ float g_encT[TT][DD][BB];      // encoder inputs transposed
__device__ float g_xdT[2][DD][BB];        // decoder input ping-pong, transposed
__device__ unsigned int g_count[NRG * 32];  // one counter per 128B
__device__ unsigned int g_gen[NRG * 32];    // monotonic generation

__device__ __forceinline__ void bar_half(int half) {
    asm volatile("bar.sync %0, %1;" :: "r"(1 + half), "r"(256) : "memory");
}

// Row-group barrier, executed by ONE 256-thread half of the CTA.
// htid = tid&255; spinner is htid==0. Replay-safe (monotonic gen).
__device__ __forceinline__ void rg_barrier(int rg, int half, int htid) {
    bar_half(half);
    if (htid == 0) {
        volatile unsigned int* genp = &g_gen[rg * 32];
        unsigned int g = *genp;
        __threadfence();
        if (atomicAdd(&g_count[rg * 32], 1u) == RGCTA - 1u) {
            g_count[rg * 32] = 0u;
            __threadfence();
            *genp = g + 1u;
        } else {
            while (*genp == g) { }
        }
        __threadfence();
    }
    bar_half(half);
}

__device__ __forceinline__ float sigm(float x) { return 1.0f / (1.0f + __expf(-x)); }

__device__ __forceinline__ ull pack2(float lo, float hi) {
    ull r; asm("mov.b64 %0, {%1, %2};" : "=l"(r) : "f"(lo), "f"(hi)); return r;
}
__device__ __forceinline__ void unpack2(ull v, float& lo, float& hi) {
    asm("mov.b64 {%0, %1}, %2;" : "=f"(lo), "=f"(hi) : "l"(v));
}
__device__ __forceinline__ void ffma2(ull& d, ull a, ull b) {
    asm("fma.rn.f32x2 %0, %1, %2, %0;" : "+l"(d) : "l"(a), "l"(b));
}

// acc[rp][j] (+)= A[k][4 rows] * W[k][8 cols]; 16 FFMA2 per k.  (R6 form)
__device__ __forceinline__ void gemm48(
    const float* __restrict__ A,
    const float* __restrict__ w,      // pre-offset to this thread's 8 cols
    int kcnt, ull acc[2][8])
{
    #pragma unroll 4
    for (int k = 0; k < kcnt; k++) {
        ulonglong2 av = *reinterpret_cast<const ulonglong2*>(A + (size_t)k * BB);
        float4 wa = *reinterpret_cast<const float4*>(w + k * 32);
        float4 wb = *reinterpret_cast<const float4*>(w + k * 32 + 4);
        ull w0 = pack2(wa.x, wa.x);
        ull w1 = pack2(wa.y, wa.y);
        ull w2 = pack2(wa.z, wa.z);
        ull w3 = pack2(wa.w, wa.w);
        ull w4 = pack2(wb.x, wb.x);
        ull w5 = pack2(wb.y, wb.y);
        ull w6 = pack2(wb.z, wb.z);
        ull w7 = pack2(wb.w, wb.w);
        ffma2(acc[0][0], av.x, w0);
        ffma2(acc[0][1], av.x, w1);
        ffma2(acc[0][2], av.x, w2);
        ffma2(acc[0][3], av.x, w3);
        ffma2(acc[0][4], av.x, w4);
        ffma2(acc[0][5], av.x, w5);
        ffma2(acc[0][6], av.x, w6);
        ffma2(acc[0][7], av.x, w7);
        ffma2(acc[1][0], av.y, w0);
        ffma2(acc[1][1], av.y, w1);
        ffma2(acc[1][2], av.y, w2);
        ffma2(acc[1][3], av.y, w3);
        ffma2(acc[1][4], av.y, w4);
        ffma2(acc[1][5], av.y, w5);
        ffma2(acc[1][6], av.y, w6);
        ffma2(acc[1][7], av.y, w7);
    }
}

// One LSTM layer step for ONE HALF: tile = 64 batch rows x 8 hidden units.
// 256 threads = 4 K-quarters x 64; quarter q writes partial z to zsh[q].
__device__ __forceinline__ void lstm_step_half(
    const float* __restrict__ Ax, int kx,          // [kx][BB] or null
    const float* __restrict__ Ah,                  // [LL][BB]
    const float* __restrict__ wsm,                 // [(kx+LL)][32]
    const float* __restrict__ bsm,
    float* __restrict__ zsh,                       // this half: [4][64][ZST]
    float c2[2],
    float* __restrict__ hOutT,                     // [LL][BB]
    int b0, int nb, int half, int htid)
{
    int q    = htid >> 6;       // K quarter
    int qtid = htid & 63;
    int tx   = qtid & 15;       // rows tx*4 .. +3 (of 64)
    int ty   = qtid >> 4;       // cols ty*8 .. +7

    ull acc[2][8];
    #pragma unroll
    for (int i = 0; i < 2; i++)
        #pragma unroll
        for (int j = 0; j < 8; j++)
            acc[i][j] = 0ull;

    int colBase = b0 + tx * 4;
    const float* wty = wsm + ty * 8;

    if (kx > 0) {
        int kq = kx >> 2;       // 32
        gemm48(Ax + colBase + (size_t)(q * kq) * BB, wty + (q * kq) * 32, kq, acc);
    }
    {
        int kq = LL >> 2;       // 64
        gemm48(Ah + colBase + (size_t)(q * kq) * BB, wty + (kx + q * kq) * 32, kq, acc);
    }

    // scalar partial-z stores (ZST=33 keeps conflicts bounded)
    float* zs = zsh + q * (64 * ZST);
    #pragma unroll
    for (int j = 0; j < 8; j++) {
        float f0, f1, f2, f3;
        unpack2(acc[0][j], f0, f1);
        unpack2(acc[1][j], f2, f3);
        int cc = ty * 8 + j;
        zs[(tx * 4 + 0) * ZST + cc] = f0;
        zs[(tx * 4 + 1) * ZST + cc] = f1;
        zs[(tx * 4 + 2) * ZST + cc] = f2;
        zs[(tx * 4 + 3) * ZST + cc] = f3;
    }
    bar_half(half);

    // activation: thread -> (2 rows, 1 unit); FIXED mapping (c lives here)
    int u  = htid >> 5;             // 0..7 (warp-uniform)
    int r0 = (htid & 31) * 2;       // 0..62
    float hv[2];
    #pragma unroll
    for (int i = 0; i < 2; i++) {
        int r = r0 + i;
        float zi = bsm[u],      zf = bsm[8 + u];
        float zg = bsm[16 + u], zo = bsm[24 + u];
        #pragma unroll
        for (int p = 0; p < 4; p++) {
            const float* zp = zsh + p * (64 * ZST) + r * ZST;
            zi += zp[u];
            zf += zp[8 + u];
            zg += zp[16 + u];
            zo += zp[24 + u];
        }
        float ig = sigm(zi);
        float fg = sigm(zf);
        float gg = fmaxf(zg, 0.0f);
        float og = sigm(zo);
        float cn = fg * c2[i] + ig * gg;
        c2[i] = cn;
        hv[i] = og * fmaxf(cn, 0.0f);
    }
    *reinterpret_cast<float2*>(&hOutT[(nb * 8 + u) * BB + b0 + r0]) =
        make_float2(hv[0], hv[1]);
    // zsm reuse is protected by the rg_barrier's bar_half after this returns
}

// Tiled transpose: encIn[b][t][k] -> g_encT[t][k][b]
extern "C" __global__ void __launch_bounds__(256)
transpose_enc_kernel(const float* __restrict__ in)
{
    __shared__ float tile[32][33];
    int t  = blockIdx.z;
    int k0 = blockIdx.y * 32;
    int b0 = blockIdx.x * 32;
    int tx = threadIdx.x, ty = threadIdx.y;  // 32 x 8
    #pragma unroll
    for (int i = 0; i < 32; i += 8)
        tile[ty + i][tx] = in[(size_t)(b0 + ty + i) * (TT * DD) + t * DD + k0 + tx];
    __syncthreads();
    #pragma unroll
    for (int i = 0; i < 32; i += 8)
        g_encT[t][k0 + ty + i][b0 + tx] = tile[tx][ty + i];
}

extern "C" __global__ void __launch_bounds__(NTHR, 1)
lstm_ae_kernel(const float* __restrict__ decIn,
               const float* __restrict__ W0, const float* __restrict__ U0, const float* __restrict__ b0g,
               const float* __restrict__ W1, const float* __restrict__ U1, const float* __restrict__ b1g,
               const float* __restrict__ Wd, const float* __restrict__ Ud, const float* __restrict__ bdg,
               const float* __restrict__ Wo, const float* __restrict__ bog,
               float* __restrict__ outp)
{
    extern __shared__ float smem[];
    float* w0sm = smem;                 // [384][32]
    float* w1sm = w0sm + 384 * 32;      // [256][32]  (W1+U1 fused: x == h for layer 1)
    float* wdsm = w1sm + 256 * 32;      // [384][32]
    float* wosm = wdsm + 384 * 32;      // [256][4]
    float* b0sm = wosm + 256 * 4;       // 32
    float* b1sm = b0sm + 32;            // 32
    float* bdsm = b1sm + 32;            // 32
    float* bosm = bdsm + 32;            // 4 (+12 pad)
    float* zsm  = bosm + 16;            // [2 halves][4][64][ZST]

    int tid = threadIdx.x;
    int nb = blockIdx.x & 31;           // hidden-unit block (8 units)
    int pr = blockIdx.x >> 5;           // pair index (0..3)

    int half = tid >> 8;                // independent recurrence A/B
    int htid = tid & 255;
    int rg = pr + half * 4;             // row group 0..7
    int b0 = rg * 64;
    float* zsh = zsm + half * ZHALF;

    // ---- one-time weight preload, layout [k][32 local cols] ----
    for (int idx = tid; idx < 384 * 32; idx += NTHR) {
        int k = idx >> 5, lc = idx & 31;
        int gcol = (lc >> 3) * LL + nb * 8 + (lc & 7);
        w0sm[idx] = (k < DD) ? W0[k * G4 + gcol] : U0[(k - DD) * G4 + gcol];
        wdsm[idx] = (k < DD) ? Wd[k * G4 + gcol] : Ud[(k - DD) * G4 + gcol];
    }
    for (int idx = tid; idx < 256 * 32; idx += NTHR) {
        int k = idx >> 5, lc = idx & 31;
        int gcol = (lc >> 3) * LL + nb * 8 + (lc & 7);
        w1sm[idx] = W1[k * G4 + gcol] + U1[k * G4 + gcol];
    }
    for (int idx = tid; idx < 256 * 4; idx += NTHR) {
        int k = idx >> 2, j = idx & 3;
        wosm[idx] = Wo[k * DD + nb * 4 + j];
    }
    if (tid < 32) {
        int gcol = (tid >> 3) * LL + nb * 8 + (tid & 7);
        b0sm[tid] = b0g[gcol];
        b1sm[tid] = b1g[gcol];
        bdsm[tid] = bdg[gcol];
    }
    if (tid < 4) bosm[tid] = bog[nb * 4 + tid];

    // init: this CTA's unit slice for BOTH its row groups
    for (int idx = tid; idx < 2 * 8 * 128; idx += NTHR) {
        int buf = idx >> 10, rem = idx & 1023;
        int f = rem >> 7, b = rem & 127;
        int grow = (pr + (b >> 6) * 4) * 64 + (b & 63);
        g_H[buf][nb * 8 + f][grow] = 0.0f;
    }
    for (int idx = tid; idx < 4 * 128; idx += NTHR) {
        int f = idx >> 7, b = idx & 127;
        int grow = (pr + (b >> 6) * 4) * 64 + (b & 63);
        g_xdT[0][nb * 4 + f][grow] = decIn[(size_t)grow * (TT * DD) + nb * 4 + f];
    }
    __syncthreads();     // full-CTA: init of BOTH halves' rows complete

    float c2[2] = {0.0f, 0.0f};
    rg_barrier(rg, half, htid);   // init visible across the row group

    int cur = 0;
    // ---------------- encoder (per half, independent progress) ----------------
    for (int t = 0; t < TT; t++) {
        lstm_step_half(&g_encT[t][0][0], DD, &g_H[cur][0][0],
                       w0sm, b0sm, zsh, c2, &g_H[cur ^ 1][0][0], b0, nb, half, htid);
        rg_barrier(rg, half, htid);
        cur ^= 1;
        lstm_step_half(nullptr, 0, &g_H[cur][0][0],
                       w1sm, b1sm, zsh, c2, &g_H[cur ^ 1][0][0], b0, nb, half, htid);
        rg_barrier(rg, half, htid);
        cur ^= 1;
    }
    // ---------------- decoder ----------------
    for (int t = 0; t < TT; t++) {
        lstm_step_half(&g_xdT[t & 1][0][0], DD, &g_H[cur][0][0],
                       wdsm, bdsm, zsh, c2, &g_H[cur ^ 1][0][0], b0, nb, half, htid);
        rg_barrier(rg, half, htid);
        cur ^= 1;

        // out = h @ out_W + out_b : 4 out-cols x 64 rows, K split in 4 chunks
        {
            int b  = htid & 63;
            int qq = htid >> 6;               // 0..3 -> K chunk of 64
            const float* hP = &g_H[cur][qq * 64][b0 + b];
            const float* wP = wosm + qq * 64 * 4;
            float s0 = 0.f, s1 = 0.f, s2 = 0.f, s3 = 0.f;
            #pragma unroll 8
            for (int kk = 0; kk < 64; kk++) {
                float h = hP[(size_t)kk * BB];
                float4 w4 = *reinterpret_cast<const float4*>(wP + kk * 4);
                s0 = fmaf(h, w4.x, s0);
                s1 = fmaf(h, w4.y, s1);
                s2 = fmaf(h, w4.z, s2);
                s3 = fmaf(h, w4.w, s3);
            }
            if (qq) {
                float* zp = zsh + ((qq - 1) * 64 + b) * 4;
                zp[0] = s0; zp[1] = s1; zp[2] = s2; zp[3] = s3;
            }
            bar_half(half);
            if (qq == 0) {
                #pragma unroll
                for (int p = 0; p < 3; p++) {
                    const float* zp = zsh + (p * 64 + b) * 4;
                    s0 += zp[0]; s1 += zp[1]; s2 += zp[2]; s3 += zp[3];
                }
                s0 += bosm[0]; s1 += bosm[1]; s2 += bosm[2]; s3 += bosm[3];
                *reinterpret_cast<float4*>(
                    outp + (size_t)(b0 + b) * (TT * DD) + t * DD + nb * 4) =
                    make_float4(s0, s1, s2, s3);
                int nxt = (t + 1) & 1;
                g_xdT[nxt][nb * 4 + 0][b0 + b] = s0;
                g_xdT[nxt][nb * 4 + 1][b0 + b] = s1;
                g_xdT[nxt][nb * 4 + 2][b0 + b] = s2;
                g_xdT[nxt][nb * 4 + 3][b0 + b] = s3;
            }
        }
        rg_barrier(rg, half, htid);
    }
}

extern "C" void kernel_launch(void* const* d_in, const int* in_sizes, int n_in,
                              void* d_out, int out_size)
{
    const float* encIn = (const float*)d_in[0];
    const float* decIn = (const float*)d_in[1];
    const float* W0    = (const float*)d_in[2];
    const float* U0    = (const float*)d_in[3];
    const float* b0    = (const float*)d_in[4];
    const float* W1    = (const float*)d_in[5];
    const float* U1    = (const float*)d_in[6];
    const float* b1    = (const float*)d_in[7];
    const float* Wd    = (const float*)d_in[8];
    const float* Ud    = (const float*)d_in[9];
    const float* bd    = (const float*)d_in[10];
    const float* Wo    = (const float*)d_in[11];
    const float* bo    = (const float*)d_in[12];
    float* outp = (float*)d_out;

    // 1) transpose encoder inputs
    {
        dim3 grid(BB / 32, DD / 32, TT);
        dim3 block(32, 8);
        transpose_enc_kernel<<<grid, block>>>(encIn);
    }

    // 2) persistent LSTM kernel
    // smem floats: 12288+8192+12288+1024+112+16 + 2*4*64*33 = 50816 (203.3KB)
    size_t smem_bytes = 50816 * sizeof(float);
    cudaFuncSetAttribute((const void*)lstm_ae_kernel,
                         cudaFuncAttributeMaxDynamicSharedMemorySize, (int)smem_bytes);
    lstm_ae_kernel<<<NCTA, NTHR, smem_bytes>>>(
        decIn, W0, U0, b0, W1, U1, b1, Wd, Ud, bd, Wo, bo, outp);
}

// round 9
// speedup vs baseline: 1.1569x; 1.0875x over previous
#include <cuda_runtime.h>

#define BB 512
#define TT 512
#define DD 128
#define LL 256
#define G4 1024
#define NCTA 128
#define NTHR 512
#define NRB 4            // row blocks
#define RBCTA 32         // CTAs per row-block barrier group
#define ZST 33           // zsm row stride (bank-conflict pad)

typedef unsigned long long ull;

// Persistent state (static __device__ globals — no allocation)
__device__ float g_H[2][LL][BB];          // hidden state [feature][batch]
__device__ float g_encT[TT][DD][BB];      // encoder inputs transposed
__device__ float g_xdT[2][DD][BB];        // decoder input ping-pong, transposed
__device__ unsigned int g_count[NRB * 32];  // one counter per 128B
__device__ unsigned int g_gen[NRB * 32];    // monotonic generation

// Split barrier over the 32 CTAs of one row block. Snapshot-based (replay-safe).
__device__ __forceinline__ void rb_arrive(int rb, unsigned int* snap) {
    __syncthreads();                     // all CTA work done before arriving
    if (threadIdx.x == 0) {
        volatile unsigned int* gp = &g_gen[rb * 32];
        *snap = *gp;                     // snapshot BEFORE own arrive
        __threadfence();
        if (atomicAdd(&g_count[rb * 32], 1u) == RBCTA - 1u) {
            g_count[rb * 32] = 0u;
            __threadfence();
            atomicAdd(&g_gen[rb * 32], 1u);   // release
        }
    }
}
__device__ __forceinline__ void rb_wait(int rb, unsigned int snap) {
    if (threadIdx.x == 0) {
        volatile unsigned int* gp = &g_gen[rb * 32];
        while (*gp == snap) { }
        __threadfence();
    }
    __syncthreads();
}

__device__ __forceinline__ float sigm(float x) { return 1.0f / (1.0f + __expf(-x)); }

__device__ __forceinline__ ull pack2(float lo, float hi) {
    ull r; asm("mov.b64 %0, {%1, %2};" : "=l"(r) : "f"(lo), "f"(hi)); return r;
}
__device__ __forceinline__ void unpack2(ull v, float& lo, float& hi) {
    asm("mov.b64 {%0, %1}, %2;" : "=f"(lo), "=f"(hi) : "l"(v));
}
__device__ __forceinline__ void ffma2(ull& d, ull a, ull b) {
    asm("fma.rn.f32x2 %0, %1, %2, %0;" : "+l"(d) : "l"(a), "l"(b));
}

// acc[rp][j] (+)= A[k][4 rows] * W[k][8 cols]; 16 FFMA2 per k.  (R6 form)
__device__ __forceinline__ void gemm48(
    const float* __restrict__ A,
    const float* __restrict__ w,      // pre-offset to this thread's 8 cols
    int kcnt, ull acc[2][8])
{
    #pragma unroll 4
    for (int k = 0; k < kcnt; k++) {
        ulonglong2 av = *reinterpret_cast<const ulonglong2*>(A + (size_t)k * BB);
        float4 wa = *reinterpret_cast<const float4*>(w + k * 32);
        float4 wb = *reinterpret_cast<const float4*>(w + k * 32 + 4);
        ull w0 = pack2(wa.x, wa.x);
        ull w1 = pack2(wa.y, wa.y);
        ull w2 = pack2(wa.z, wa.z);
        ull w3 = pack2(wa.w, wa.w);
        ull w4 = pack2(wb.x, wb.x);
        ull w5 = pack2(wb.y, wb.y);
        ull w6 = pack2(wb.z, wb.z);
        ull w7 = pack2(wb.w, wb.w);
        ffma2(acc[0][0], av.x, w0);
        ffma2(acc[0][1], av.x, w1);
        ffma2(acc[0][2], av.x, w2);
        ffma2(acc[0][3], av.x, w3);
        ffma2(acc[0][4], av.x, w4);
        ffma2(acc[0][5], av.x, w5);
        ffma2(acc[0][6], av.x, w6);
        ffma2(acc[0][7], av.x, w7);
        ffma2(acc[1][0], av.y, w0);
        ffma2(acc[1][1], av.y, w1);
        ffma2(acc[1][2], av.y, w2);
        ffma2(acc[1][3], av.y, w3);
        ffma2(acc[1][4], av.y, w4);
        ffma2(acc[1][5], av.y, w5);
        ffma2(acc[1][6], av.y, w6);
        ffma2(acc[1][7], av.y, w7);
    }
}

__device__ __forceinline__ void acc_zero(ull acc[2][8]) {
    #pragma unroll
    for (int i = 0; i < 2; i++)
        #pragma unroll
        for (int j = 0; j < 8; j++)
            acc[i][j] = 0ull;
}

// scalar partial-z stores (ZST=33 keeps conflicts at 4-way)
__device__ __forceinline__ void z_store(float* zs, int tx, int ty, const ull acc[2][8]) {
    #pragma unroll
    for (int j = 0; j < 8; j++) {
        float f0, f1, f2, f3;
        unpack2(acc[0][j], f0, f1);
        unpack2(acc[1][j], f2, f3);
        int cc = ty * 8 + j;
        zs[(tx * 4 + 0) * ZST + cc] = f0;
        zs[(tx * 4 + 1) * ZST + cc] = f1;
        zs[(tx * 4 + 2) * ZST + cc] = f2;
        zs[(tx * 4 + 3) * ZST + cc] = f3;
    }
}

// activation: thread -> (2 rows, 1 unit); FIXED mapping (c lives here)
__device__ __forceinline__ void activation(
    const float* __restrict__ zsm, const float* __restrict__ bsm,
    float c2[2], float* __restrict__ hOutT, int b0, int nb, int tid)
{
    int u  = tid >> 6;              // 0..7
    int r0 = (tid & 63) * 2;
    float hv[2];
    #pragma unroll
    for (int i = 0; i < 2; i++) {
        int r = r0 + i;
        float zi = bsm[u],      zf = bsm[8 + u];
        float zg = bsm[16 + u], zo = bsm[24 + u];
        #pragma unroll
        for (int p = 0; p < 4; p++) {
            const float* zp = zsm + p * (128 * ZST) + r * ZST;
            zi += zp[u];
            zf += zp[8 + u];
            zg += zp[16 + u];
            zo += zp[24 + u];
        }
        float ig = sigm(zi);
        float fg = sigm(zf);
        float gg = fmaxf(zg, 0.0f);
        float og = sigm(zo);
        float cn = fg * c2[i] + ig * gg;
        c2[i] = cn;
        hv[i] = og * fmaxf(cn, 0.0f);
    }
    *reinterpret_cast<float2*>(&hOutT[(nb * 8 + u) * BB + b0 + r0]) =
        make_float2(hv[0], hv[1]);
}

// Tiled transpose: encIn[b][t][k] -> g_encT[t][k][b]
extern "C" __global__ void __launch_bounds__(256)
transpose_enc_kernel(const float* __restrict__ in)
{
    __shared__ float tile[32][33];
    int t  = blockIdx.z;
    int k0 = blockIdx.y * 32;
    int b0 = blockIdx.x * 32;
    int tx = threadIdx.x, ty = threadIdx.y;  // 32 x 8
    #pragma unroll
    for (int i = 0; i < 32; i += 8)
        tile[ty + i][tx] = in[(size_t)(b0 + ty + i) * (TT * DD) + t * DD + k0 + tx];
    __syncthreads();
    #pragma unroll
    for (int i = 0; i < 32; i += 8)
        g_encT[t][k0 + ty + i][b0 + tx] = tile[tx][ty + i];
}

extern "C" __global__ void __launch_bounds__(NTHR, 1)
lstm_ae_kernel(const float* __restrict__ decIn,
               const float* __restrict__ W0, const float* __restrict__ U0, const float* __restrict__ b0g,
               const float* __restrict__ W1, const float* __restrict__ U1, const float* __restrict__ b1g,
               const float* __restrict__ Wd, const float* __restrict__ Ud, const float* __restrict__ bdg,
               const float* __restrict__ Wo, const float* __restrict__ bog,
               float* __restrict__ outp)
{
    extern __shared__ float smem[];
    float* w0sm = smem;                 // [384][32]
    float* w1sm = w0sm + 384 * 32;      // [256][32]  (W1+U1 fused: x == h for layer 1)
    float* wdsm = w1sm + 256 * 32;      // [384][32]
    float* wosm = wdsm + 384 * 32;      // [256][4]
    float* b0sm = wosm + 256 * 4;       // 32
    float* b1sm = b0sm + 32;            // 32
    float* bdsm = b1sm + 32;            // 32
    float* bosm = bdsm + 32;            // 4 (+12 pad)
    float* zsm  = bosm + 16;            // [4][128][ZST]

    int tid = threadIdx.x;
    int nb = blockIdx.x & 31;           // hidden-unit block (8 units)
    int rb = blockIdx.x >> 5;           // row block (128 batch rows)
    int b0 = rb * 128;

    int q    = tid >> 7;                // K quarter
    int qtid = tid & 127;
    int tx   = qtid & 31;               // rows tx*4 .. +3
    int ty   = qtid >> 5;               // cols ty*8 .. +7 (warp-uniform)
    int colBase = b0 + tx * 4;
    float* zq = zsm + q * (128 * ZST);
    const float* w0ty = w0sm + ty * 8;
    const float* w1ty = w1sm + ty * 8;
    const float* wdty = wdsm + ty * 8;

    // ---- one-time weight preload, layout [k][32 local cols] ----
    for (int idx = tid; idx < 384 * 32; idx += NTHR) {
        int k = idx >> 5, lc = idx & 31;
        int gcol = (lc >> 3) * LL + nb * 8 + (lc & 7);
        w0sm[idx] = (k < DD) ? W0[k * G4 + gcol] : U0[(k - DD) * G4 + gcol];
        wdsm[idx] = (k < DD) ? Wd[k * G4 + gcol] : Ud[(k - DD) * G4 + gcol];
    }
    for (int idx = tid; idx < 256 * 32; idx += NTHR) {
        int k = idx >> 5, lc = idx & 31;
        int gcol = (lc >> 3) * LL + nb * 8 + (lc & 7);
        w1sm[idx] = W1[k * G4 + gcol] + U1[k * G4 + gcol];
    }
    for (int idx = tid; idx < 256 * 4; idx += NTHR) {
        int k = idx >> 2, j = idx & 3;
        wosm[idx] = Wo[k * DD + nb * 4 + j];
    }
    if (tid < 32) {
        int gcol = (tid >> 3) * LL + nb * 8 + (tid & 7);
        b0sm[tid] = b0g[gcol];
        b1sm[tid] = b1g[gcol];
        bdsm[tid] = bdg[gcol];
    }
    if (tid < 4) bosm[tid] = bog[nb * 4 + tid];

    // init: each CTA owns its (feature-slice x batch-slice) of g_H / g_xdT.
    for (int idx = tid; idx < 2 * 8 * 128; idx += NTHR) {
        int buf = idx >> 10, f = (idx >> 7) & 7, b = idx & 127;
        g_H[buf][nb * 8 + f][b0 + b] = 0.0f;
    }
    for (int idx = tid; idx < 4 * 128; idx += NTHR) {
        int f = idx >> 7, b = idx & 127;
        g_xdT[0][nb * 4 + f][b0 + b] = decIn[(size_t)(b0 + b) * (TT * DD) + nb * 4 + f];
    }
    __syncthreads();   // weights visible before prologue x-gemm

    float c2[2] = {0.0f, 0.0f};
    unsigned int snap;

    // x-partials for encoder t=0 accumulate in registers (depends only on g_encT)
    ull acc[2][8];
    acc_zero(acc);
    gemm48(&g_encT[0][q * 32][colBase], w0ty + (q * 32) * 32, 32, acc);

    rb_arrive(rb, &snap);   // init barrier (H, xdT visible)

    int cur = 0;
    // ---------------- encoder ----------------
    for (int t = 0; t < TT; t++) {
        // ===== layer 0: acc already holds x_t @ W0 partials =====
        rb_wait(rb, snap);                         // h_L1(t-1) visible
        gemm48(&g_H[cur][q * 64][colBase], w0ty + (DD + q * 64) * 32, 64, acc);
        z_store(zq, tx, ty, acc);
        __syncthreads();
        activation(zsm, b0sm, c2, &g_H[cur ^ 1][0][0], b0, nb, tid);
        rb_arrive(rb, &snap);                      // h_L0(t) posted
        cur ^= 1;

        // ===== layer 1: z = h' @ (W1+U1) =====
        rb_wait(rb, snap);                         // h_L0(t) all visible
        acc_zero(acc);
        gemm48(&g_H[cur][q * 64][colBase], w1ty + (q * 64) * 32, 64, acc);
        z_store(zq, tx, ty, acc);
        __syncthreads();
        activation(zsm, b1sm, c2, &g_H[cur ^ 1][0][0], b0, nb, tid);
        rb_arrive(rb, &snap);                      // h_L1(t) posted
        cur ^= 1;

        // ===== overlap: next step's x-partials in REGISTERS while barrier settles
        acc_zero(acc);
        if (t + 1 < TT)
            gemm48(&g_encT[t + 1][q * 32][colBase], w0ty + (q * 32) * 32, 32, acc);
    }
    // ---------------- decoder ----------------
    for (int t = 0; t < TT; t++) {
        rb_wait(rb, snap);                         // h(t-1) + xdT(t) visible
        acc_zero(acc);
        gemm48(&g_xdT[t & 1][q * 32][colBase], wdty + (q * 32) * 32, 32, acc);
        gemm48(&g_H[cur][q * 64][colBase], wdty + (DD + q * 64) * 32, 64, acc);
        z_store(zq, tx, ty, acc);
        __syncthreads();
        activation(zsm, bdsm, c2, &g_H[cur ^ 1][0][0], b0, nb, tid);
        rb_arrive(rb, &snap);                      // h_dec(t) posted
        cur ^= 1;
        rb_wait(rb, snap);                         // all h_dec(t) visible

        // out = h @ out_W + out_b : 4 out-cols x 128 rows, K split in 4 chunks
        {
            int b  = tid & 127;
            int qq = tid >> 7;                     // 0..3 -> K chunk of 64
            const float* hP = &g_H[cur][qq * 64][b0 + b];
            const float* wP = wosm + qq * 64 * 4;
            float s0 = 0.f, s1 = 0.f, s2 = 0.f, s3 = 0.f;
            #pragma unroll 8
            for (int kk = 0; kk < 64; kk++) {
                float h = hP[(size_t)kk * BB];
                float4 w4 = *reinterpret_cast<const float4*>(wP + kk * 4);
                s0 = fmaf(h, w4.x, s0);
                s1 = fmaf(h, w4.y, s1);
                s2 = fmaf(h, w4.z, s2);
                s3 = fmaf(h, w4.w, s3);
            }
            if (qq) {
                float* zp = zsm + ((qq - 1) * 128 + b) * 4;
                zp[0] = s0; zp[1] = s1; zp[2] = s2; zp[3] = s3;
            }
            __syncthreads();
            if (qq == 0) {
                #pragma unroll
                for (int p = 0; p < 3; p++) {
                    const float* zp = zsm + (p * 128 + b) * 4;
                    s0 += zp[0]; s1 += zp[1]; s2 += zp[2]; s3 += zp[3];
                }
                s0 += bosm[0]; s1 += bosm[1]; s2 += bosm[2]; s3 += bosm[3];
                *reinterpret_cast<float4*>(
                    outp + (size_t)(b0 + b) * (TT * DD) + t * DD + nb * 4) =
                    make_float4(s0, s1, s2, s3);
                int nxt = (t + 1) & 1;
                g_xdT[nxt][nb * 4 + 0][b0 + b] = s0;
                g_xdT[nxt][nb * 4 + 1][b0 + b] = s1;
                g_xdT[nxt][nb * 4 + 2][b0 + b] = s2;
                g_xdT[nxt][nb * 4 + 3][b0 + b] = s3;
            }
        }
        rb_arrive(rb, &snap);                      // out(t)/xdT(t+1) posted
    }
}

extern "C" void kernel_launch(void* const* d_in, const int* in_sizes, int n_in,
                              void* d_out, int out_size)
{
    const float* encIn = (const float*)d_in[0];
    const float* decIn = (const float*)d_in[1];
    const float* W0    = (const float*)d_in[2];
    const float* U0    = (const float*)d_in[3];
    const float* b0    = (const float*)d_in[4];
    const float* W1    = (const float*)d_in[5];
    const float* U1    = (const float*)d_in[6];
    const float* b1    = (const float*)d_in[7];
    const float* Wd    = (const float*)d_in[8];
    const float* Ud    = (const float*)d_in[9];
    const float* bd    = (const float*)d_in[10];
    const float* Wo    = (const float*)d_in[11];
    const float* bo    = (const float*)d_in[12];
    float* outp = (float*)d_out;

    // 1) transpose encoder inputs
    {
        dim3 grid(BB / 32, DD / 32, TT);
        dim3 block(32, 8);
        transpose_enc_kernel<<<grid, block>>>(encIn);
    }

    // 2) persistent LSTM kernel
    // smem floats: 12288+8192+12288+1024+112+16 + 4*128*33 = 50800 (203.2KB)
    size_t smem_bytes = 50800 * sizeof(float);
    cudaFuncSetAttribute((const void*)lstm_ae_kernel,
                         cudaFuncAttributeMaxDynamicSharedMemorySize, (int)smem_bytes);
    lstm_ae_kernel<<<NCTA, NTHR, smem_bytes>>>(
        decIn, W0, U0, b0, W1, U1, b1, Wd, Ud, bd, Wo, bo, outp);
}